// round 1
// baseline (speedup 1.0000x reference)
#include <cuda_runtime.h>
#include <math.h>

// Problem constants
#define BATCH 8192
#define TFR   19      // T_COND + L
#define LFR   15
#define KSEL  5
#define VOC   128
#define INF   45      // L*D
#define HID   1024
#define OUTF  512
#define ROWS  (BATCH*KSEL)   // 40960

// ---------------- scratch (static device allocations; no cudaMalloc) -------
__device__ float g_Xo[(size_t)ROWS * INF];        // offset MLP inputs
__device__ int   g_ids[ROWS];                     // selected vocab ids
__device__ float g_tableV[VOC * OUTF];            // precomputed vocab-branch MLP
__device__ float g_H[(size_t)ROWS * HID];         // post-LN hidden of MLP_o

__device__ __forceinline__ float gelu_f(float x) {
    return 0.5f * x * (1.0f + erff(x * 0.7071067811865476f));
}

// ===========================================================================
// Kernel A: per-batch rel-traj (only f = F-1), top-5 vocab select, offsets
// ===========================================================================
__global__ __launch_bounds__(128) void preproc_kernel(
    const float* __restrict__ poses, const float* __restrict__ vocab)
{
    __shared__ float s_vocab[VOC * INF];     // 23 KB
    __shared__ float s_traj[128 * INF];      // 23 KB
    int tid = threadIdx.x;
    for (int i = tid; i < VOC * INF; i += 128) s_vocab[i] = vocab[i];
    __syncthreads();

    int b = blockIdx.x * 128 + tid;
    const float* p3 = poses + ((size_t)b * TFR + 3) * 16;
    float R[9], t3[3];
    #pragma unroll
    for (int i = 0; i < 3; i++) {
        R[i*3+0] = p3[i*4+0]; R[i*3+1] = p3[i*4+1]; R[i*3+2] = p3[i*4+2];
        t3[i] = p3[i*4+3];
    }
    float* tr = &s_traj[tid * INF];
    #pragma unroll
    for (int j = 0; j < LFR; j++) {
        const float* pg = poses + ((size_t)b * TFR + 4 + j) * 16;
        float g00 = pg[0], g10 = pg[4], g20 = pg[8];
        float dx = pg[3] - t3[0], dy = pg[7] - t3[1], dz = pg[11] - t3[2];
        // (R3^T d)_i = sum_k R3[k][i] d_k
        float relx = R[0]*dx + R[3]*dy + R[6]*dz;
        float rely = R[1]*dx + R[4]*dy + R[7]*dz;
        float rr00 = R[0]*g00 + R[3]*g10 + R[6]*g20;
        float rr10 = R[1]*g00 + R[4]*g10 + R[7]*g20;
        tr[j*3+0] = relx; tr[j*3+1] = rely; tr[j*3+2] = atan2f(rr10, rr00);
    }

    // top-5 smallest distance (squared; monotone), stable tie -> lower index
    float tx = tr[42], ty = tr[43], tz = tr[44];
    float bd[KSEL]; int bi[KSEL];
    #pragma unroll
    for (int k = 0; k < KSEL; k++) { bd[k] = 3.4e38f; bi[k] = -1; }
    for (int v = 0; v < VOC; v++) {
        float ax = tx - s_vocab[v*INF+42];
        float ay = ty - s_vocab[v*INF+43];
        float az = tz - s_vocab[v*INF+44];
        float d2 = ax*ax + ay*ay + az*az;
        if (d2 < bd[KSEL-1]) {
            int p = KSEL-1;
            while (p > 0 && bd[p-1] > d2) { bd[p] = bd[p-1]; bi[p] = bi[p-1]; p--; }
            bd[p] = d2; bi[p] = v;
        }
    }
    #pragma unroll
    for (int k = 0; k < KSEL; k++) {
        int v = bi[k];
        g_ids[b*KSEL + k] = v;
        float* xo = &g_Xo[(size_t)(b*KSEL + k) * INF];
        const float* vv = &s_vocab[v*INF];
        for (int i = 0; i < INF; i++) xo[i] = tr[i] - vv[i];
    }
}

// ===========================================================================
// Kernel B: vocab-branch MLP table (128 rows only)
// ===========================================================================
__global__ __launch_bounds__(256) void vocab_mlp_kernel(
    const float* __restrict__ vocab,
    const float* __restrict__ w1, const float* __restrict__ b1,
    const float* __restrict__ g,  const float* __restrict__ be,
    const float* __restrict__ w2, const float* __restrict__ b2)
{
    __shared__ float s_x[INF];
    __shared__ float s_h[HID];
    __shared__ float s_red[16];
    __shared__ float s_mu, s_rstd;
    int v = blockIdx.x, tid = threadIdx.x;
    if (tid < INF) {
        float val = vocab[v*INF + tid];
        int d = tid % 3;
        float nv;
        if (d == 0)      nv = 2.0f*(val + 1.57f)/66.74f - 1.0f;
        else if (d == 1) nv = 2.0f*(val + 19.68f)/42.0f - 1.0f;
        else             nv = 2.0f*(val + 1.67f)/3.53f - 1.0f;
        s_x[tid] = nv;
    }
    __syncthreads();

    int j0 = tid * 4;
    float4 acc = *(const float4*)&b1[j0];
    for (int i = 0; i < INF; i++) {
        float xv = s_x[i];
        const float4 w = *(const float4*)&w1[i*HID + j0];
        acc.x += xv*w.x; acc.y += xv*w.y; acc.z += xv*w.z; acc.w += xv*w.w;
    }
    acc.x = gelu_f(acc.x); acc.y = gelu_f(acc.y);
    acc.z = gelu_f(acc.z); acc.w = gelu_f(acc.w);

    float lsum = acc.x + acc.y + acc.z + acc.w;
    float lss  = acc.x*acc.x + acc.y*acc.y + acc.z*acc.z + acc.w*acc.w;
    for (int o = 16; o; o >>= 1) {
        lsum += __shfl_down_sync(0xffffffffu, lsum, o);
        lss  += __shfl_down_sync(0xffffffffu, lss,  o);
    }
    if ((tid & 31) == 0) { s_red[tid>>5] = lsum; s_red[8 + (tid>>5)] = lss; }
    __syncthreads();
    if (tid == 0) {
        float sm = 0.f, ss = 0.f;
        for (int w = 0; w < 8; w++) { sm += s_red[w]; ss += s_red[8+w]; }
        float mu = sm / HID;
        s_mu = mu; s_rstd = rsqrtf(ss / HID - mu*mu + 1e-5f);
    }
    __syncthreads();
    float mu = s_mu, rstd = s_rstd;
    const float4 gg = *(const float4*)&g[j0];
    const float4 bb = *(const float4*)&be[j0];
    s_h[j0+0] = (acc.x - mu)*rstd*gg.x + bb.x;
    s_h[j0+1] = (acc.y - mu)*rstd*gg.y + bb.y;
    s_h[j0+2] = (acc.z - mu)*rstd*gg.z + bb.z;
    s_h[j0+3] = (acc.w - mu)*rstd*gg.w + bb.w;
    __syncthreads();

    float o1 = b2[tid], o2 = b2[tid + 256];
    for (int i = 0; i < HID; i++) {
        float hv = s_h[i];
        o1 += hv * w2[i*OUTF + tid];
        o2 += hv * w2[i*OUTF + tid + 256];
    }
    g_tableV[v*OUTF + tid]       = o1;
    g_tableV[v*OUTF + tid + 256] = o2;
}

// ===========================================================================
// Kernel C: MLP_o layer1 + GELU + LayerNorm -> g_H   (8 rows per block)
// ===========================================================================
__global__ __launch_bounds__(256) void layer1_kernel(
    const float* __restrict__ w1, const float* __restrict__ b1,
    const float* __restrict__ g,  const float* __restrict__ be)
{
    __shared__ float sx[8][INF];
    __shared__ float s_part[8][8][2];
    __shared__ float s_mu[8], s_rstd[8];
    int tid = threadIdx.x;
    int row0 = blockIdx.x * 8;
    for (int i = tid; i < 8*INF; i += 256)
        sx[i/INF][i%INF] = g_Xo[(size_t)row0*INF + i];
    __syncthreads();

    int j0 = tid * 4;
    float4 bb1 = *(const float4*)&b1[j0];
    float acc[8][4];
    #pragma unroll
    for (int r = 0; r < 8; r++) {
        acc[r][0]=bb1.x; acc[r][1]=bb1.y; acc[r][2]=bb1.z; acc[r][3]=bb1.w;
    }
    for (int i = 0; i < INF; i++) {
        const float4 w = *(const float4*)&w1[i*HID + j0];
        #pragma unroll
        for (int r = 0; r < 8; r++) {
            float xv = sx[r][i];
            acc[r][0] += xv*w.x; acc[r][1] += xv*w.y;
            acc[r][2] += xv*w.z; acc[r][3] += xv*w.w;
        }
    }
    int wid = tid >> 5, lane = tid & 31;
    #pragma unroll
    for (int r = 0; r < 8; r++) {
        float s = 0.f, ss = 0.f;
        #pragma unroll
        for (int c = 0; c < 4; c++) {
            float h = gelu_f(acc[r][c]);
            acc[r][c] = h; s += h; ss += h*h;
        }
        for (int o = 16; o; o >>= 1) {
            s  += __shfl_down_sync(0xffffffffu, s,  o);
            ss += __shfl_down_sync(0xffffffffu, ss, o);
        }
        if (lane == 0) { s_part[wid][r][0] = s; s_part[wid][r][1] = ss; }
    }
    __syncthreads();
    if (tid < 8) {
        float s = 0.f, ss = 0.f;
        for (int w = 0; w < 8; w++) { s += s_part[w][tid][0]; ss += s_part[w][tid][1]; }
        float mu = s / HID;
        s_mu[tid] = mu;
        s_rstd[tid] = rsqrtf(ss / HID - mu*mu + 1e-5f);
    }
    __syncthreads();
    const float4 gg = *(const float4*)&g[j0];
    const float4 bb = *(const float4*)&be[j0];
    #pragma unroll
    for (int r = 0; r < 8; r++) {
        float mu = s_mu[r], rstd = s_rstd[r];
        float4 o;
        o.x = (acc[r][0]-mu)*rstd*gg.x + bb.x;
        o.y = (acc[r][1]-mu)*rstd*gg.y + bb.y;
        o.z = (acc[r][2]-mu)*rstd*gg.z + bb.z;
        o.w = (acc[r][3]-mu)*rstd*gg.w + bb.w;
        *(float4*)&g_H[(size_t)(row0+r)*HID + j0] = o;
    }
}

// ===========================================================================
// Kernel D: layer2 SGEMM  C[40960x512] = H[40960x1024] @ W2[1024x512]
//           + b2 + gathered vocab table.  BM=128 BN=64 BK=16, 8x4/thread.
// ===========================================================================
__global__ __launch_bounds__(256) void gemm2_kernel(
    const float* __restrict__ w2, const float* __restrict__ b2,
    float* __restrict__ out)
{
    __shared__ float As[16][132];   // [BK][BM+4]
    __shared__ float Bs[16][64];    // [BK][BN]
    int tid = threadIdx.x;
    int tx = tid & 15;              // N direction, 16 x 4
    int ty = tid >> 4;              // M direction, 16 x 8
    int row0 = blockIdx.y * 128;
    int n0   = blockIdx.x * 64;

    float acc[8][4];
    #pragma unroll
    for (int m = 0; m < 8; m++)
        #pragma unroll
        for (int n = 0; n < 4; n++) acc[m][n] = 0.f;

    for (int kt = 0; kt < HID/16; kt++) {
        int k0 = kt * 16;
        // load A tile (128x16), transpose into As[k][m]
        #pragma unroll
        for (int it = 0; it < 2; it++) {
            int fid = tid*2 + it;
            int m = fid >> 2;
            int kq = (fid & 3) * 4;
            float4 v = *(const float4*)(g_H + (size_t)(row0 + m)*HID + k0 + kq);
            As[kq+0][m] = v.x; As[kq+1][m] = v.y;
            As[kq+2][m] = v.z; As[kq+3][m] = v.w;
        }
        // load B tile (16x64)
        {
            int kb = tid >> 4;
            int nq = (tid & 15) * 4;
            *(float4*)&Bs[kb][nq] = *(const float4*)(w2 + (size_t)(k0 + kb)*OUTF + n0 + nq);
        }
        __syncthreads();
        #pragma unroll
        for (int kk = 0; kk < 16; kk++) {
            float4 a0 = *(const float4*)&As[kk][ty*8];
            float4 a1 = *(const float4*)&As[kk][ty*8 + 4];
            float4 b  = *(const float4*)&Bs[kk][tx*4];
            float am[8] = {a0.x,a0.y,a0.z,a0.w,a1.x,a1.y,a1.z,a1.w};
            float bn[4] = {b.x,b.y,b.z,b.w};
            #pragma unroll
            for (int m = 0; m < 8; m++)
                #pragma unroll
                for (int n = 0; n < 4; n++)
                    acc[m][n] += am[m]*bn[n];
        }
        __syncthreads();
    }

    const float4 bb = *(const float4*)(b2 + n0 + tx*4);
    #pragma unroll
    for (int m = 0; m < 8; m++) {
        int row = row0 + ty*8 + m;
        int vid = g_ids[row];
        const float4 tv = *(const float4*)(g_tableV + vid*OUTF + n0 + tx*4);
        float4 o;
        o.x = acc[m][0] + bb.x + tv.x;
        o.y = acc[m][1] + bb.y + tv.y;
        o.z = acc[m][2] + bb.z + tv.z;
        o.w = acc[m][3] + bb.w + tv.w;
        *(float4*)(out + (size_t)row*OUTF + n0 + tx*4) = o;
    }
}

// ===========================================================================
extern "C" void kernel_launch(void* const* d_in, const int* in_sizes, int n_in,
                              void* d_out, int out_size)
{
    const float* poses = (const float*)d_in[0];
    const float* vocab = (const float*)d_in[1];
    const float* w1_v  = (const float*)d_in[2];
    const float* b1_v  = (const float*)d_in[3];
    const float* g_v   = (const float*)d_in[4];
    const float* be_v  = (const float*)d_in[5];
    const float* w2_v  = (const float*)d_in[6];
    const float* b2_v  = (const float*)d_in[7];
    const float* w1_o  = (const float*)d_in[8];
    const float* b1_o  = (const float*)d_in[9];
    const float* g_o   = (const float*)d_in[10];
    const float* be_o  = (const float*)d_in[11];
    const float* w2_o  = (const float*)d_in[12];
    const float* b2_o  = (const float*)d_in[13];
    float* out = (float*)d_out;

    preproc_kernel<<<BATCH/128, 128>>>(poses, vocab);
    vocab_mlp_kernel<<<VOC, 256>>>(vocab, w1_v, b1_v, g_v, be_v, w2_v, b2_v);
    layer1_kernel<<<ROWS/8, 256>>>(w1_o, b1_o, g_o, be_o);
    gemm2_kernel<<<dim3(OUTF/64, ROWS/128), 256>>>(w2_o, b2_o, out);
}

// round 4
// speedup vs baseline: 2.8146x; 2.8146x over previous
#include <cuda_runtime.h>
#include <cuda_fp16.h>
#include <math.h>
#include <stdint.h>

// Problem constants
#define BATCH 8192
#define TFR   19
#define LFR   15
#define KSEL  5
#define VOC   128
#define INF   45
#define HID   1024
#define OUTF  512
#define ROWS  (BATCH*KSEL)   // 40960

// ---------------- scratch ---------------------------------------------------
__device__ float  g_Xo[(size_t)ROWS * INF];
__device__ int    g_ids[ROWS];
__device__ float  g_tableV[VOC * OUTF];
__device__ __half g_Hh[(size_t)ROWS * HID];     // post-LN hidden, fp16
__device__ __half g_W2t[(size_t)OUTF * HID];    // W2 transposed [N][K] fp16

__device__ __forceinline__ float gelu_f(float x) {
    return 0.5f * x * (1.0f + erff(x * 0.7071067811865476f));
}

__device__ __forceinline__ uint32_t smem_to_u32(const void* p) {
    uint32_t a;
    asm("{ .reg .u64 t; cvta.to.shared.u64 t, %1; cvt.u32.u64 %0, t; }"
        : "=r"(a) : "l"(p));
    return a;
}
__device__ __forceinline__ void cp_async16(uint32_t dst, const void* src) {
    asm volatile("cp.async.cg.shared.global [%0], [%1], 16;" :: "r"(dst), "l"(src));
}
#define CP_COMMIT() asm volatile("cp.async.commit_group;" ::: "memory")
#define CP_WAIT0()  asm volatile("cp.async.wait_group 0;" ::: "memory")
#define CP_WAIT1()  asm volatile("cp.async.wait_group 1;" ::: "memory")

__device__ __forceinline__ void ldsm_x4(uint32_t& r0, uint32_t& r1,
                                        uint32_t& r2, uint32_t& r3, uint32_t addr) {
    asm volatile("ldmatrix.sync.aligned.m8n8.x4.shared.b16 {%0,%1,%2,%3}, [%4];"
        : "=r"(r0), "=r"(r1), "=r"(r2), "=r"(r3) : "r"(addr));
}
__device__ __forceinline__ void mma16816(float& c0, float& c1, float& c2, float& c3,
                                         uint32_t a0, uint32_t a1, uint32_t a2, uint32_t a3,
                                         uint32_t b0, uint32_t b1) {
    asm volatile(
        "mma.sync.aligned.m16n8k16.row.col.f32.f16.f16.f32 "
        "{%0,%1,%2,%3}, {%4,%5,%6,%7}, {%8,%9}, {%0,%1,%2,%3};"
        : "+f"(c0), "+f"(c1), "+f"(c2), "+f"(c3)
        : "r"(a0), "r"(a1), "r"(a2), "r"(a3), "r"(b0), "r"(b1));
}

// ===========================================================================
// Kernel A: per-batch rel-traj (only f = F-1), top-5 vocab select, offsets
// ===========================================================================
__global__ __launch_bounds__(128) void preproc_kernel(
    const float* __restrict__ poses, const float* __restrict__ vocab)
{
    __shared__ float s_vocab[VOC * INF];
    __shared__ float s_traj[128 * INF];
    int tid = threadIdx.x;
    for (int i = tid; i < VOC * INF; i += 128) s_vocab[i] = vocab[i];
    __syncthreads();

    int b = blockIdx.x * 128 + tid;
    const float* p3 = poses + ((size_t)b * TFR + 3) * 16;
    float R[9], t3[3];
    #pragma unroll
    for (int i = 0; i < 3; i++) {
        R[i*3+0] = p3[i*4+0]; R[i*3+1] = p3[i*4+1]; R[i*3+2] = p3[i*4+2];
        t3[i] = p3[i*4+3];
    }
    float* tr = &s_traj[tid * INF];
    #pragma unroll
    for (int j = 0; j < LFR; j++) {
        const float* pg = poses + ((size_t)b * TFR + 4 + j) * 16;
        float g00 = pg[0], g10 = pg[4], g20 = pg[8];
        float dx = pg[3] - t3[0], dy = pg[7] - t3[1], dz = pg[11] - t3[2];
        float relx = R[0]*dx + R[3]*dy + R[6]*dz;
        float rely = R[1]*dx + R[4]*dy + R[7]*dz;
        float rr00 = R[0]*g00 + R[3]*g10 + R[6]*g20;
        float rr10 = R[1]*g00 + R[4]*g10 + R[7]*g20;
        tr[j*3+0] = relx; tr[j*3+1] = rely; tr[j*3+2] = atan2f(rr10, rr00);
    }

    float tx = tr[42], ty = tr[43], tz = tr[44];
    float bd[KSEL]; int bi[KSEL];
    #pragma unroll
    for (int k = 0; k < KSEL; k++) { bd[k] = 3.4e38f; bi[k] = -1; }
    for (int v = 0; v < VOC; v++) {
        float ax = tx - s_vocab[v*INF+42];
        float ay = ty - s_vocab[v*INF+43];
        float az = tz - s_vocab[v*INF+44];
        float d2 = ax*ax + ay*ay + az*az;
        if (d2 < bd[KSEL-1]) {
            int p = KSEL-1;
            while (p > 0 && bd[p-1] > d2) { bd[p] = bd[p-1]; bi[p] = bi[p-1]; p--; }
            bd[p] = d2; bi[p] = v;
        }
    }
    #pragma unroll
    for (int k = 0; k < KSEL; k++) {
        int v = bi[k];
        g_ids[b*KSEL + k] = v;
        float* xo = &g_Xo[(size_t)(b*KSEL + k) * INF];
        const float* vv = &s_vocab[v*INF];
        for (int i = 0; i < INF; i++) xo[i] = tr[i] - vv[i];
    }
}

// ===========================================================================
// Kernel B: vocab-branch MLP table (128 rows only)
// ===========================================================================
__global__ __launch_bounds__(256) void vocab_mlp_kernel(
    const float* __restrict__ vocab,
    const float* __restrict__ w1, const float* __restrict__ b1,
    const float* __restrict__ g,  const float* __restrict__ be,
    const float* __restrict__ w2, const float* __restrict__ b2)
{
    __shared__ float s_x[INF];
    __shared__ float s_h[HID];
    __shared__ float s_red[16];
    __shared__ float s_mu, s_rstd;
    int v = blockIdx.x, tid = threadIdx.x;
    if (tid < INF) {
        float val = vocab[v*INF + tid];
        int d = tid % 3;
        float nv;
        if (d == 0)      nv = 2.0f*(val + 1.57f)/66.74f - 1.0f;
        else if (d == 1) nv = 2.0f*(val + 19.68f)/42.0f - 1.0f;
        else             nv = 2.0f*(val + 1.67f)/3.53f - 1.0f;
        s_x[tid] = nv;
    }
    __syncthreads();

    int j0 = tid * 4;
    float4 acc = *(const float4*)&b1[j0];
    for (int i = 0; i < INF; i++) {
        float xv = s_x[i];
        const float4 w = *(const float4*)&w1[i*HID + j0];
        acc.x += xv*w.x; acc.y += xv*w.y; acc.z += xv*w.z; acc.w += xv*w.w;
    }
    acc.x = gelu_f(acc.x); acc.y = gelu_f(acc.y);
    acc.z = gelu_f(acc.z); acc.w = gelu_f(acc.w);

    float lsum = acc.x + acc.y + acc.z + acc.w;
    float lss  = acc.x*acc.x + acc.y*acc.y + acc.z*acc.z + acc.w*acc.w;
    for (int o = 16; o; o >>= 1) {
        lsum += __shfl_down_sync(0xffffffffu, lsum, o);
        lss  += __shfl_down_sync(0xffffffffu, lss,  o);
    }
    if ((tid & 31) == 0) { s_red[tid>>5] = lsum; s_red[8 + (tid>>5)] = lss; }
    __syncthreads();
    if (tid == 0) {
        float sm = 0.f, ss = 0.f;
        for (int w = 0; w < 8; w++) { sm += s_red[w]; ss += s_red[8+w]; }
        float mu = sm / HID;
        s_mu = mu; s_rstd = rsqrtf(ss / HID - mu*mu + 1e-5f);
    }
    __syncthreads();
    float mu = s_mu, rstd = s_rstd;
    const float4 gg = *(const float4*)&g[j0];
    const float4 bb = *(const float4*)&be[j0];
    s_h[j0+0] = (acc.x - mu)*rstd*gg.x + bb.x;
    s_h[j0+1] = (acc.y - mu)*rstd*gg.y + bb.y;
    s_h[j0+2] = (acc.z - mu)*rstd*gg.z + bb.z;
    s_h[j0+3] = (acc.w - mu)*rstd*gg.w + bb.w;
    __syncthreads();

    float o1 = b2[tid], o2 = b2[tid + 256];
    for (int i = 0; i < HID; i++) {
        float hv = s_h[i];
        o1 += hv * w2[i*OUTF + tid];
        o2 += hv * w2[i*OUTF + tid + 256];
    }
    g_tableV[v*OUTF + tid]       = o1;
    g_tableV[v*OUTF + tid + 256] = o2;
}

// ===========================================================================
// Kernel B2: W2 transpose + fp16 convert:  g_W2t[n][k] = half(w2[k][n])
// ===========================================================================
__global__ __launch_bounds__(256) void w2t_kernel(const float* __restrict__ w2)
{
    __shared__ float t[32][33];
    int k0 = blockIdx.x * 32, n0 = blockIdx.y * 32;
    int tx = threadIdx.x & 31, ty = threadIdx.x >> 5;
    #pragma unroll
    for (int i = 0; i < 4; i++) {
        int k = ty + i * 8;
        t[k][tx] = w2[(size_t)(k0 + k) * OUTF + n0 + tx];
    }
    __syncthreads();
    #pragma unroll
    for (int i = 0; i < 4; i++) {
        int n = ty + i * 8;
        g_W2t[(size_t)(n0 + n) * HID + k0 + tx] = __float2half(t[tx][n]);
    }
}

// ===========================================================================
// Kernel C: MLP_o layer1 + GELU + LayerNorm -> g_Hh (fp16)
// ===========================================================================
__global__ __launch_bounds__(256) void layer1_kernel(
    const float* __restrict__ w1, const float* __restrict__ b1,
    const float* __restrict__ g,  const float* __restrict__ be)
{
    __shared__ float sx[8][INF];
    __shared__ float s_part[8][8][2];
    __shared__ float s_mu[8], s_rstd[8];
    int tid = threadIdx.x;
    int row0 = blockIdx.x * 8;
    for (int i = tid; i < 8*INF; i += 256)
        sx[i/INF][i%INF] = g_Xo[(size_t)row0*INF + i];
    __syncthreads();

    int j0 = tid * 4;
    float4 bb1 = *(const float4*)&b1[j0];
    float acc[8][4];
    #pragma unroll
    for (int r = 0; r < 8; r++) {
        acc[r][0]=bb1.x; acc[r][1]=bb1.y; acc[r][2]=bb1.z; acc[r][3]=bb1.w;
    }
    for (int i = 0; i < INF; i++) {
        const float4 w = *(const float4*)&w1[i*HID + j0];
        #pragma unroll
        for (int r = 0; r < 8; r++) {
            float xv = sx[r][i];
            acc[r][0] += xv*w.x; acc[r][1] += xv*w.y;
            acc[r][2] += xv*w.z; acc[r][3] += xv*w.w;
        }
    }
    int wid = tid >> 5, lane = tid & 31;
    #pragma unroll
    for (int r = 0; r < 8; r++) {
        float s = 0.f, ss = 0.f;
        #pragma unroll
        for (int c = 0; c < 4; c++) {
            float h = gelu_f(acc[r][c]);
            acc[r][c] = h; s += h; ss += h*h;
        }
        for (int o = 16; o; o >>= 1) {
            s  += __shfl_down_sync(0xffffffffu, s,  o);
            ss += __shfl_down_sync(0xffffffffu, ss, o);
        }
        if (lane == 0) { s_part[wid][r][0] = s; s_part[wid][r][1] = ss; }
    }
    __syncthreads();
    if (tid < 8) {
        float s = 0.f, ss = 0.f;
        for (int w = 0; w < 8; w++) { s += s_part[w][tid][0]; ss += s_part[w][tid][1]; }
        float mu = s / HID;
        s_mu[tid] = mu;
        s_rstd[tid] = rsqrtf(ss / HID - mu*mu + 1e-5f);
    }
    __syncthreads();
    const float4 gg = *(const float4*)&g[j0];
    const float4 bb = *(const float4*)&be[j0];
    #pragma unroll
    for (int r = 0; r < 8; r++) {
        float mu = s_mu[r], rstd = s_rstd[r];
        float ox = (acc[r][0]-mu)*rstd*gg.x + bb.x;
        float oy = (acc[r][1]-mu)*rstd*gg.y + bb.y;
        float oz = (acc[r][2]-mu)*rstd*gg.z + bb.z;
        float ow = (acc[r][3]-mu)*rstd*gg.w + bb.w;
        __half2 h01 = __floats2half2_rn(ox, oy);
        __half2 h23 = __floats2half2_rn(oz, ow);
        uint2 u;
        u.x = *reinterpret_cast<uint32_t*>(&h01);
        u.y = *reinterpret_cast<uint32_t*>(&h23);
        *(uint2*)&g_Hh[(size_t)(row0+r)*HID + j0] = u;
    }
}

// ===========================================================================
// Kernel D: HMMA fp16 GEMM  C[40960x512] = Hh @ W2t^T  (+ b2 + table)
// BM=128 BN=128 BK=32, 8 warps (2x4), 64x32 per warp, double-buffered cp.async
// ===========================================================================
#define BK   32
#define NK   (HID / BK)         // 32
#define APAD 8                  // row stride 40 halves = 80B (conflict-free ldsm)
#define ASTR (BK + APAD)

__global__ __launch_bounds__(256) void gemm2_mma_kernel(
    const float* __restrict__ b2, float* __restrict__ out)
{
    __shared__ __half As[2][128][ASTR];
    __shared__ __half Bs[2][128][ASTR];

    int tid = threadIdx.x;
    int wid = tid >> 5, lane = tid & 31;
    int warp_m = wid & 1;        // 0..1 -> 64 rows each
    int warp_n = wid >> 1;       // 0..3 -> 32 cols each
    int row0 = blockIdx.y * 128;
    int n0   = blockIdx.x * 128;

    uint32_t as_u = smem_to_u32(As);
    uint32_t bs_u = smem_to_u32(Bs);
    const uint32_t stageBytes = 128 * ASTR * 2;

    float acc[4][4][4];
    #pragma unroll
    for (int mt = 0; mt < 4; mt++)
        #pragma unroll
        for (int nt = 0; nt < 4; nt++)
            #pragma unroll
            for (int c = 0; c < 4; c++) acc[mt][nt][c] = 0.f;

    auto load_tiles = [&](int stage, int kt) {
        int k0 = kt * BK;
        #pragma unroll
        for (int i = 0; i < 2; i++) {
            int idx = tid + i * 256;       // 0..511
            int r = idx >> 2, c = (idx & 3) * 8;
            cp_async16(as_u + stage * stageBytes + (r * ASTR + c) * 2,
                       &g_Hh[(size_t)(row0 + r) * HID + k0 + c]);
            cp_async16(bs_u + stage * stageBytes + (r * ASTR + c) * 2,
                       &g_W2t[(size_t)(n0 + r) * HID + k0 + c]);
        }
    };

    load_tiles(0, 0);
    CP_COMMIT();

    // ldmatrix lane addressing (element offsets within a stage)
    int a_row = warp_m * 64 + (lane & 15);      // + mt*16
    int a_col = (lane >> 4) * 8;                // + k
    int b_row = warp_n * 32 + ((lane >> 4) << 3) + (lane & 7);  // + p*16
    int b_col = ((lane >> 3) & 1) * 8;          // + k

    for (int kt = 0; kt < NK; kt++) {
        int cur = kt & 1;
        if (kt + 1 < NK) {
            load_tiles(cur ^ 1, kt + 1);
            CP_COMMIT();
            CP_WAIT1();
        } else {
            CP_WAIT0();
        }
        __syncthreads();

        uint32_t aBase = as_u + cur * stageBytes;
        uint32_t bBase = bs_u + cur * stageBytes;
        #pragma unroll
        for (int ks = 0; ks < 2; ks++) {
            int k = ks * 16;
            uint32_t af[4][4];
            #pragma unroll
            for (int mt = 0; mt < 4; mt++) {
                uint32_t addr = aBase + ((a_row + mt * 16) * ASTR + a_col + k) * 2;
                ldsm_x4(af[mt][0], af[mt][1], af[mt][2], af[mt][3], addr);
            }
            uint32_t bf[4][2];
            #pragma unroll
            for (int p = 0; p < 2; p++) {
                uint32_t addr = bBase + ((b_row + p * 16) * ASTR + b_col + k) * 2;
                uint32_t r0, r1, r2, r3;
                ldsm_x4(r0, r1, r2, r3, addr);
                bf[p*2+0][0] = r0; bf[p*2+0][1] = r1;
                bf[p*2+1][0] = r2; bf[p*2+1][1] = r3;
            }
            #pragma unroll
            for (int mt = 0; mt < 4; mt++)
                #pragma unroll
                for (int nt = 0; nt < 4; nt++)
                    mma16816(acc[mt][nt][0], acc[mt][nt][1],
                             acc[mt][nt][2], acc[mt][nt][3],
                             af[mt][0], af[mt][1], af[mt][2], af[mt][3],
                             bf[nt][0], bf[nt][1]);
        }
        __syncthreads();
    }

    // Epilogue: + b2 + gathered vocab table, write fp32
    int r_in = lane >> 2;
    int c_in = (lane & 3) * 2;
    #pragma unroll
    for (int mt = 0; mt < 4; mt++) {
        #pragma unroll
        for (int h = 0; h < 2; h++) {
            int row = row0 + warp_m * 64 + mt * 16 + h * 8 + r_in;
            int vid = g_ids[row];
            const float* tv = g_tableV + (size_t)vid * OUTF;
            float* orow = out + (size_t)row * OUTF;
            #pragma unroll
            for (int nt = 0; nt < 4; nt++) {
                int col = n0 + warp_n * 32 + nt * 8 + c_in;
                float2 bb = *(const float2*)&b2[col];
                float2 tt = *(const float2*)&tv[col];
                float2 o;
                o.x = acc[mt][nt][h*2+0] + bb.x + tt.x;
                o.y = acc[mt][nt][h*2+1] + bb.y + tt.y;
                *(float2*)&orow[col] = o;
            }
        }
    }
}

// ===========================================================================
extern "C" void kernel_launch(void* const* d_in, const int* in_sizes, int n_in,
                              void* d_out, int out_size)
{
    const float* poses = (const float*)d_in[0];
    const float* vocab = (const float*)d_in[1];
    const float* w1_v  = (const float*)d_in[2];
    const float* b1_v  = (const float*)d_in[3];
    const float* g_v   = (const float*)d_in[4];
    const float* be_v  = (const float*)d_in[5];
    const float* w2_v  = (const float*)d_in[6];
    const float* b2_v  = (const float*)d_in[7];
    const float* w1_o  = (const float*)d_in[8];
    const float* b1_o  = (const float*)d_in[9];
    const float* g_o   = (const float*)d_in[10];
    const float* be_o  = (const float*)d_in[11];
    const float* w2_o  = (const float*)d_in[12];
    const float* b2_o  = (const float*)d_in[13];
    float* out = (float*)d_out;

    preproc_kernel<<<BATCH/128, 128>>>(poses, vocab);
    vocab_mlp_kernel<<<VOC, 256>>>(vocab, w1_v, b1_v, g_v, be_v, w2_v, b2_v);
    w2t_kernel<<<dim3(HID/32, OUTF/32), 256>>>(w2_o);
    layer1_kernel<<<ROWS/8, 256>>>(w1_o, b1_o, g_o, be_o);
    gemm2_mma_kernel<<<dim3(OUTF/128, ROWS/128), 256>>>(b2_o, out);
}

// round 7
// speedup vs baseline: 2.9957x; 1.0643x over previous
#include <cuda_runtime.h>
#include <cuda_fp16.h>
#include <math.h>
#include <stdint.h>

// Problem constants
#define BATCH 8192
#define TFR   19
#define LFR   15
#define KSEL  5
#define VOC   128
#define INF   45
#define HID   1024
#define OUTF  512
#define ROWS  (BATCH*KSEL)   // 40960
#define KP    48             // padded K for layer1
#define KSTR  56             // smem row stride (halves) for layer1 tiles

// ---------------- scratch ---------------------------------------------------
__device__ __half g_Xh[(size_t)ROWS * KP];      // padded fp16 MLP_o inputs
__device__ int    g_ids[ROWS];
__device__ float  g_tableV[VOC * OUTF];
__device__ __half g_W1t[HID * KP];              // W1 transposed [N][Kp] fp16
__device__ __half g_Hh[(size_t)ROWS * HID];     // post-LN hidden, fp16
__device__ __half g_W2t[(size_t)OUTF * HID];    // W2 transposed [N][K] fp16

__device__ __forceinline__ float gelu_f(float x) {
    return 0.5f * x * (1.0f + erff(x * 0.7071067811865476f));
}

__device__ __forceinline__ uint32_t smem_to_u32(const void* p) {
    uint32_t a;
    asm("{ .reg .u64 t; cvta.to.shared.u64 t, %1; cvt.u32.u64 %0, t; }"
        : "=r"(a) : "l"(p));
    return a;
}
__device__ __forceinline__ void cp_async16(uint32_t dst, const void* src) {
    asm volatile("cp.async.cg.shared.global [%0], [%1], 16;" :: "r"(dst), "l"(src));
}
#define CP_COMMIT() asm volatile("cp.async.commit_group;" ::: "memory")
#define CP_WAIT0()  asm volatile("cp.async.wait_group 0;" ::: "memory")
#define CP_WAIT1()  asm volatile("cp.async.wait_group 1;" ::: "memory")

__device__ __forceinline__ void ldsm_x4(uint32_t& r0, uint32_t& r1,
                                        uint32_t& r2, uint32_t& r3, uint32_t addr) {
    asm volatile("ldmatrix.sync.aligned.m8n8.x4.shared.b16 {%0,%1,%2,%3}, [%4];"
        : "=r"(r0), "=r"(r1), "=r"(r2), "=r"(r3) : "r"(addr));
}
__device__ __forceinline__ void mma16816(float& c0, float& c1, float& c2, float& c3,
                                         uint32_t a0, uint32_t a1, uint32_t a2, uint32_t a3,
                                         uint32_t b0, uint32_t b1) {
    asm volatile(
        "mma.sync.aligned.m16n8k16.row.col.f32.f16.f16.f32 "
        "{%0,%1,%2,%3}, {%4,%5,%6,%7}, {%8,%9}, {%0,%1,%2,%3};"
        : "+f"(c0), "+f"(c1), "+f"(c2), "+f"(c3)
        : "r"(a0), "r"(a1), "r"(a2), "r"(a3), "r"(b0), "r"(b1));
}

// ===========================================================================
// Kernel A: per-batch rel-traj (only f = F-1), top-5 vocab select, offsets
// ===========================================================================
__global__ __launch_bounds__(128) void preproc_kernel(
    const float* __restrict__ poses, const float* __restrict__ vocab)
{
    __shared__ float s_vocab[VOC * INF];
    __shared__ float s_traj[128 * INF];
    int tid = threadIdx.x;
    for (int i = tid; i < VOC * INF; i += 128) s_vocab[i] = vocab[i];
    __syncthreads();

    int b = blockIdx.x * 128 + tid;
    const float* p3 = poses + ((size_t)b * TFR + 3) * 16;
    float R[9], t3[3];
    #pragma unroll
    for (int i = 0; i < 3; i++) {
        R[i*3+0] = p3[i*4+0]; R[i*3+1] = p3[i*4+1]; R[i*3+2] = p3[i*4+2];
        t3[i] = p3[i*4+3];
    }
    float* tr = &s_traj[tid * INF];
    #pragma unroll
    for (int j = 0; j < LFR; j++) {
        const float* pg = poses + ((size_t)b * TFR + 4 + j) * 16;
        float g00 = pg[0], g10 = pg[4], g20 = pg[8];
        float dx = pg[3] - t3[0], dy = pg[7] - t3[1], dz = pg[11] - t3[2];
        float relx = R[0]*dx + R[3]*dy + R[6]*dz;
        float rely = R[1]*dx + R[4]*dy + R[7]*dz;
        float rr00 = R[0]*g00 + R[3]*g10 + R[6]*g20;
        float rr10 = R[1]*g00 + R[4]*g10 + R[7]*g20;
        tr[j*3+0] = relx; tr[j*3+1] = rely; tr[j*3+2] = atan2f(rr10, rr00);
    }

    float tx = tr[42], ty = tr[43], tz = tr[44];
    float bd[KSEL]; int bi[KSEL];
    #pragma unroll
    for (int k = 0; k < KSEL; k++) { bd[k] = 3.4e38f; bi[k] = -1; }
    for (int v = 0; v < VOC; v++) {
        float ax = tx - s_vocab[v*INF+42];
        float ay = ty - s_vocab[v*INF+43];
        float az = tz - s_vocab[v*INF+44];
        float d2 = ax*ax + ay*ay + az*az;
        if (d2 < bd[KSEL-1]) {
            int p = KSEL-1;
            while (p > 0 && bd[p-1] > d2) { bd[p] = bd[p-1]; bi[p] = bi[p-1]; p--; }
            bd[p] = d2; bi[p] = v;
        }
    }
    #pragma unroll
    for (int k = 0; k < KSEL; k++) {
        int v = bi[k];
        g_ids[b*KSEL + k] = v;
        __half* xo = &g_Xh[(size_t)(b*KSEL + k) * KP];
        const float* vv = &s_vocab[v*INF];
        for (int i = 0; i < INF; i++) xo[i] = __float2half(tr[i] - vv[i]);
        xo[45] = __float2half(0.f); xo[46] = __float2half(0.f); xo[47] = __float2half(0.f);
    }
}

// ===========================================================================
// Kernel B: vocab-branch MLP table (128 rows only)
// ===========================================================================
__global__ __launch_bounds__(256) void vocab_mlp_kernel(
    const float* __restrict__ vocab,
    const float* __restrict__ w1, const float* __restrict__ b1,
    const float* __restrict__ g,  const float* __restrict__ be,
    const float* __restrict__ w2, const float* __restrict__ b2)
{
    __shared__ float s_x[INF];
    __shared__ float s_h[HID];
    __shared__ float s_red[16];
    __shared__ float s_mu, s_rstd;
    int v = blockIdx.x, tid = threadIdx.x;
    if (tid < INF) {
        float val = vocab[v*INF + tid];
        int d = tid % 3;
        float nv;
        if (d == 0)      nv = 2.0f*(val + 1.57f)/66.74f - 1.0f;
        else if (d == 1) nv = 2.0f*(val + 19.68f)/42.0f - 1.0f;
        else             nv = 2.0f*(val + 1.67f)/3.53f - 1.0f;
        s_x[tid] = nv;
    }
    __syncthreads();

    int j0 = tid * 4;
    float4 acc = *(const float4*)&b1[j0];
    for (int i = 0; i < INF; i++) {
        float xv = s_x[i];
        const float4 w = *(const float4*)&w1[i*HID + j0];
        acc.x += xv*w.x; acc.y += xv*w.y; acc.z += xv*w.z; acc.w += xv*w.w;
    }
    acc.x = gelu_f(acc.x); acc.y = gelu_f(acc.y);
    acc.z = gelu_f(acc.z); acc.w = gelu_f(acc.w);

    float lsum = acc.x + acc.y + acc.z + acc.w;
    float lss  = acc.x*acc.x + acc.y*acc.y + acc.z*acc.z + acc.w*acc.w;
    for (int o = 16; o; o >>= 1) {
        lsum += __shfl_down_sync(0xffffffffu, lsum, o);
        lss  += __shfl_down_sync(0xffffffffu, lss,  o);
    }
    if ((tid & 31) == 0) { s_red[tid>>5] = lsum; s_red[8 + (tid>>5)] = lss; }
    __syncthreads();
    if (tid == 0) {
        float sm = 0.f, ss = 0.f;
        for (int w = 0; w < 8; w++) { sm += s_red[w]; ss += s_red[8+w]; }
        float mu = sm / HID;
        s_mu = mu; s_rstd = rsqrtf(ss / HID - mu*mu + 1e-5f);
    }
    __syncthreads();
    float mu = s_mu, rstd = s_rstd;
    const float4 gg = *(const float4*)&g[j0];
    const float4 bb = *(const float4*)&be[j0];
    s_h[j0+0] = (acc.x - mu)*rstd*gg.x + bb.x;
    s_h[j0+1] = (acc.y - mu)*rstd*gg.y + bb.y;
    s_h[j0+2] = (acc.z - mu)*rstd*gg.z + bb.z;
    s_h[j0+3] = (acc.w - mu)*rstd*gg.w + bb.w;
    __syncthreads();

    float o1 = b2[tid], o2 = b2[tid + 256];
    for (int i = 0; i < HID; i++) {
        float hv = s_h[i];
        o1 += hv * w2[i*OUTF + tid];
        o2 += hv * w2[i*OUTF + tid + 256];
    }
    g_tableV[v*OUTF + tid]       = o1;
    g_tableV[v*OUTF + tid + 256] = o2;
}

// ===========================================================================
// Kernel B2: W2 transpose + fp16:  g_W2t[n][k] = half(w2[k][n])
// ===========================================================================
__global__ __launch_bounds__(256) void w2t_kernel(const float* __restrict__ w2)
{
    __shared__ float t[32][33];
    int k0 = blockIdx.x * 32, n0 = blockIdx.y * 32;
    int tx = threadIdx.x & 31, ty = threadIdx.x >> 5;
    #pragma unroll
    for (int i = 0; i < 4; i++) {
        int k = ty + i * 8;
        t[k][tx] = w2[(size_t)(k0 + k) * OUTF + n0 + tx];
    }
    __syncthreads();
    #pragma unroll
    for (int i = 0; i < 4; i++) {
        int n = ty + i * 8;
        g_W2t[(size_t)(n0 + n) * HID + k0 + tx] = __float2half(t[tx][n]);
    }
}

// ===========================================================================
// Kernel B3: W1 transpose + fp16 + pad:  g_W1t[n][k] (k<45) else 0
// ===========================================================================
__global__ __launch_bounds__(256) void w1t_kernel(const float* __restrict__ w1)
{
    int idx = blockIdx.x * 256 + threadIdx.x;    // HID*KP = 49152
    if (idx >= HID * KP) return;
    int n = idx / KP, k = idx % KP;
    g_W1t[idx] = (k < INF) ? __float2half(w1[(size_t)k * HID + n])
                           : __float2half(0.f);
}

// ===========================================================================
// Kernel C: layer1 via HMMA + fused bias/GELU/LayerNorm -> g_Hh (fp16)
// Persistent blocks: W1t (112 KB) staged in SMEM once, loop over 32-row tiles.
// 8 warps; warp w covers cols [w*128, w*128+128); 2 m-tiles x 16 n-tiles.
// ===========================================================================
#define L1_ROWS  32
#define L1_TILES (ROWS / L1_ROWS)     // 1280
#define SM_W1   0
#define SM_A    (HID * KSTR * 2)                  // 114688
#define SM_B1   (SM_A + L1_ROWS * KSTR * 2)       // 118272
#define SM_G    (SM_B1 + HID * 4)                 // 122368
#define SM_BE   (SM_G + HID * 4)                  // 126464
#define SM_RED  (SM_BE + HID * 4)                 // 130560 (8*32*2 floats)
#define SM_MU   (SM_RED + 8 * 32 * 2 * 4)         // 132608
#define SM_RSTD (SM_MU + 32 * 4)                  // 132736
#define SM_L1_TOT (SM_RSTD + 32 * 4)              // 132864

__global__ __launch_bounds__(256, 1) void layer1_tc_kernel(
    const float* __restrict__ b1, const float* __restrict__ g,
    const float* __restrict__ be)
{
    extern __shared__ char sm[];
    float* sB1  = (float*)(sm + SM_B1);
    float* sG   = (float*)(sm + SM_G);
    float* sBe  = (float*)(sm + SM_BE);
    float* sRed = (float*)(sm + SM_RED);
    float* sMu  = (float*)(sm + SM_MU);
    float* sRstd= (float*)(sm + SM_RSTD);

    int tid = threadIdx.x, wid = tid >> 5, lane = tid & 31;
    uint32_t sW1u = smem_to_u32(sm) + SM_W1;
    uint32_t sAu  = smem_to_u32(sm) + SM_A;

    // stage W1t + biases once
    for (int idx = tid; idx < HID * 6; idx += 256) {
        int n = idx / 6, c = idx % 6;
        cp_async16(sW1u + (n * KSTR + c * 8) * 2, &g_W1t[n * KP + c * 8]);
    }
    for (int i = tid; i < HID; i += 256) {
        sB1[i] = b1[i]; sG[i] = g[i]; sBe[i] = be[i];
    }
    CP_COMMIT(); CP_WAIT0();
    __syncthreads();

    int n_base = wid * 128;
    int quad = lane >> 2;            // 0..7 (row within 8)
    int qlan = lane & 3;             // col pair within quad

    for (int tile = blockIdx.x; tile < L1_TILES; tile += gridDim.x) {
        int row0 = tile * L1_ROWS;
        __syncthreads();             // sA/sRed reuse guard
        for (int idx = tid; idx < L1_ROWS * 6; idx += 256) {
            int r = idx / 6, c = idx % 6;
            cp_async16(sAu + (r * KSTR + c * 8) * 2,
                       &g_Xh[(size_t)(row0 + r) * KP + c * 8]);
        }
        CP_COMMIT(); CP_WAIT0();
        __syncthreads();

        float acc[2][16][4];
        #pragma unroll
        for (int m = 0; m < 2; m++)
            #pragma unroll
            for (int nt = 0; nt < 16; nt++)
                #pragma unroll
                for (int c = 0; c < 4; c++) acc[m][nt][c] = 0.f;

        #pragma unroll
        for (int ks = 0; ks < 3; ks++) {
            uint32_t af[2][4];
            #pragma unroll
            for (int m = 0; m < 2; m++) {
                uint32_t addr = sAu +
                    ((m * 16 + (lane & 15)) * KSTR + (lane >> 4) * 8 + ks * 16) * 2;
                ldsm_x4(af[m][0], af[m][1], af[m][2], af[m][3], addr);
            }
            #pragma unroll
            for (int p = 0; p < 8; p++) {
                uint32_t b0, b1_, b2_, b3_;
                uint32_t addr = sW1u +
                    ((n_base + p * 16 + ((lane >> 4) << 3) + (lane & 7)) * KSTR
                     + ((lane >> 3) & 1) * 8 + ks * 16) * 2;
                ldsm_x4(b0, b1_, b2_, b3_, addr);
                #pragma unroll
                for (int m = 0; m < 2; m++) {
                    mma16816(acc[m][2*p][0],   acc[m][2*p][1],
                             acc[m][2*p][2],   acc[m][2*p][3],
                             af[m][0], af[m][1], af[m][2], af[m][3], b0, b1_);
                    mma16816(acc[m][2*p+1][0], acc[m][2*p+1][1],
                             acc[m][2*p+1][2], acc[m][2*p+1][3],
                             af[m][0], af[m][1], af[m][2], af[m][3], b2_, b3_);
                }
            }
        }

        // bias + GELU + per-row partial sums
        float sums[4] = {0.f, 0.f, 0.f, 0.f};
        float ssq[4]  = {0.f, 0.f, 0.f, 0.f};
        #pragma unroll
        for (int m = 0; m < 2; m++) {
            #pragma unroll
            for (int nt = 0; nt < 16; nt++) {
                int col = n_base + nt * 8 + 2 * qlan;
                #pragma unroll
                for (int c = 0; c < 4; c++) {
                    float v = acc[m][nt][c] + sB1[col + (c & 1)];
                    float h = gelu_f(v);
                    acc[m][nt][c] = h;
                    int rg = m * 2 + (c >> 1);
                    sums[rg] += h; ssq[rg] += h * h;
                }
            }
        }
        #pragma unroll
        for (int rg = 0; rg < 4; rg++) {
            sums[rg] += __shfl_xor_sync(0xffffffffu, sums[rg], 1);
            sums[rg] += __shfl_xor_sync(0xffffffffu, sums[rg], 2);
            ssq[rg]  += __shfl_xor_sync(0xffffffffu, ssq[rg], 1);
            ssq[rg]  += __shfl_xor_sync(0xffffffffu, ssq[rg], 2);
        }
        if (qlan == 0) {
            #pragma unroll
            for (int rg = 0; rg < 4; rg++) {
                int lr = (rg >> 1) * 16 + quad + (rg & 1) * 8;
                sRed[(wid * 32 + lr) * 2 + 0] = sums[rg];
                sRed[(wid * 32 + lr) * 2 + 1] = ssq[rg];
            }
        }
        __syncthreads();
        if (tid < 32) {
            float s = 0.f, ss = 0.f;
            #pragma unroll
            for (int w = 0; w < 8; w++) {
                s  += sRed[(w * 32 + tid) * 2 + 0];
                ss += sRed[(w * 32 + tid) * 2 + 1];
            }
            float mu = s / HID;
            sMu[tid] = mu;
            sRstd[tid] = rsqrtf(ss / HID - mu * mu + 1e-5f);
        }
        __syncthreads();

        #pragma unroll
        for (int m = 0; m < 2; m++) {
            int r0 = m * 16 + quad;
            int r1 = r0 + 8;
            float mu0 = sMu[r0], rs0 = sRstd[r0];
            float mu1 = sMu[r1], rs1 = sRstd[r1];
            #pragma unroll
            for (int nt = 0; nt < 16; nt++) {
                int col = n_base + nt * 8 + 2 * qlan;
                float g0 = sG[col], g1 = sG[col + 1];
                float e0 = sBe[col], e1 = sBe[col + 1];
                __half2 h0 = __floats2half2_rn(
                    (acc[m][nt][0] - mu0) * rs0 * g0 + e0,
                    (acc[m][nt][1] - mu0) * rs0 * g1 + e1);
                __half2 h1 = __floats2half2_rn(
                    (acc[m][nt][2] - mu1) * rs1 * g0 + e0,
                    (acc[m][nt][3] - mu1) * rs1 * g1 + e1);
                *(__half2*)&g_Hh[(size_t)(row0 + r0) * HID + col] = h0;
                *(__half2*)&g_Hh[(size_t)(row0 + r1) * HID + col] = h1;
            }
        }
    }
}

// ===========================================================================
// Kernel D: HMMA fp16 GEMM  C[40960x512] = Hh @ W2t^T  (+ b2 + table)
// BM=128 BN=128 BK=32, 8 warps (2x4), 64x32 per warp, double-buffered cp.async
// ===========================================================================
#define BK   32
#define NK   (HID / BK)         // 32
#define APAD 8
#define ASTR (BK + APAD)

__global__ __launch_bounds__(256) void gemm2_mma_kernel(
    const float* __restrict__ b2, float* __restrict__ out)
{
    __shared__ __half As[2][128][ASTR];
    __shared__ __half Bs[2][128][ASTR];

    int tid = threadIdx.x;
    int wid = tid >> 5, lane = tid & 31;
    int warp_m = wid & 1;
    int warp_n = wid >> 1;
    int row0 = blockIdx.y * 128;
    int n0   = blockIdx.x * 128;

    uint32_t as_u = smem_to_u32(As);
    uint32_t bs_u = smem_to_u32(Bs);
    const uint32_t stageBytes = 128 * ASTR * 2;

    float acc[4][4][4];
    #pragma unroll
    for (int mt = 0; mt < 4; mt++)
        #pragma unroll
        for (int nt = 0; nt < 4; nt++)
            #pragma unroll
            for (int c = 0; c < 4; c++) acc[mt][nt][c] = 0.f;

    auto load_tiles = [&](int stage, int kt) {
        int k0 = kt * BK;
        #pragma unroll
        for (int i = 0; i < 2; i++) {
            int idx = tid + i * 256;
            int r = idx >> 2, c = (idx & 3) * 8;
            cp_async16(as_u + stage * stageBytes + (r * ASTR + c) * 2,
                       &g_Hh[(size_t)(row0 + r) * HID + k0 + c]);
            cp_async16(bs_u + stage * stageBytes + (r * ASTR + c) * 2,
                       &g_W2t[(size_t)(n0 + r) * HID + k0 + c]);
        }
    };

    load_tiles(0, 0);
    CP_COMMIT();

    int a_row = warp_m * 64 + (lane & 15);
    int a_col = (lane >> 4) * 8;
    int b_row = warp_n * 32 + ((lane >> 4) << 3) + (lane & 7);
    int b_col = ((lane >> 3) & 1) * 8;

    for (int kt = 0; kt < NK; kt++) {
        int cur = kt & 1;
        if (kt + 1 < NK) {
            load_tiles(cur ^ 1, kt + 1);
            CP_COMMIT();
            CP_WAIT1();
        } else {
            CP_WAIT0();
        }
        __syncthreads();

        uint32_t aBase = as_u + cur * stageBytes;
        uint32_t bBase = bs_u + cur * stageBytes;
        #pragma unroll
        for (int ks = 0; ks < 2; ks++) {
            int k = ks * 16;
            uint32_t af[4][4];
            #pragma unroll
            for (int mt = 0; mt < 4; mt++) {
                uint32_t addr = aBase + ((a_row + mt * 16) * ASTR + a_col + k) * 2;
                ldsm_x4(af[mt][0], af[mt][1], af[mt][2], af[mt][3], addr);
            }
            uint32_t bf[4][2];
            #pragma unroll
            for (int p = 0; p < 2; p++) {
                uint32_t addr = bBase + ((b_row + p * 16) * ASTR + b_col + k) * 2;
                uint32_t r0, r1, r2, r3;
                ldsm_x4(r0, r1, r2, r3, addr);
                bf[p*2+0][0] = r0; bf[p*2+0][1] = r1;
                bf[p*2+1][0] = r2; bf[p*2+1][1] = r3;
            }
            #pragma unroll
            for (int mt = 0; mt < 4; mt++)
                #pragma unroll
                for (int nt = 0; nt < 4; nt++)
                    mma16816(acc[mt][nt][0], acc[mt][nt][1],
                             acc[mt][nt][2], acc[mt][nt][3],
                             af[mt][0], af[mt][1], af[mt][2], af[mt][3],
                             bf[nt][0], bf[nt][1]);
        }
        __syncthreads();
    }

    int r_in = lane >> 2;
    int c_in = (lane & 3) * 2;
    #pragma unroll
    for (int mt = 0; mt < 4; mt++) {
        #pragma unroll
        for (int h = 0; h < 2; h++) {
            int row = row0 + warp_m * 64 + mt * 16 + h * 8 + r_in;
            int vid = g_ids[row];
            const float* tv = g_tableV + (size_t)vid * OUTF;
            float* orow = out + (size_t)row * OUTF;
            #pragma unroll
            for (int nt = 0; nt < 4; nt++) {
                int col = n0 + warp_n * 32 + nt * 8 + c_in;
                float2 bb = *(const float2*)&b2[col];
                float2 tt = *(const float2*)&tv[col];
                float2 o;
                o.x = acc[mt][nt][h*2+0] + bb.x + tt.x;
                o.y = acc[mt][nt][h*2+1] + bb.y + tt.y;
                *(float2*)&orow[col] = o;
            }
        }
    }
}

// ===========================================================================
extern "C" void kernel_launch(void* const* d_in, const int* in_sizes, int n_in,
                              void* d_out, int out_size)
{
    const float* poses = (const float*)d_in[0];
    const float* vocab = (const float*)d_in[1];
    const float* w1_v  = (const float*)d_in[2];
    const float* b1_v  = (const float*)d_in[3];
    const float* g_v   = (const float*)d_in[4];
    const float* be_v  = (const float*)d_in[5];
    const float* w2_v  = (const float*)d_in[6];
    const float* b2_v  = (const float*)d_in[7];
    const float* w1_o  = (const float*)d_in[8];
    const float* b1_o  = (const float*)d_in[9];
    const float* g_o   = (const float*)d_in[10];
    const float* be_o  = (const float*)d_in[11];
    const float* w2_o  = (const float*)d_in[12];
    const float* b2_o  = (const float*)d_in[13];
    float* out = (float*)d_out;

    cudaFuncSetAttribute(layer1_tc_kernel,
                         cudaFuncAttributeMaxDynamicSharedMemorySize, SM_L1_TOT);

    preproc_kernel<<<BATCH/128, 128>>>(poses, vocab);
    vocab_mlp_kernel<<<VOC, 256>>>(vocab, w1_v, b1_v, g_v, be_v, w2_v, b2_v);
    w1t_kernel<<<(HID*KP + 255)/256, 256>>>(w1_o);
    w2t_kernel<<<dim3(HID/32, OUTF/32), 256>>>(w2_o);
    layer1_tc_kernel<<<148, 256, SM_L1_TOT>>>(b1_o, g_o, be_o);
    gemm2_mma_kernel<<<dim3(OUTF/128, ROWS/128), 256>>>(b2_o, out);
}